// round 6
// baseline (speedup 1.0000x reference)
#include <cuda_runtime.h>
#include <math.h>

#define MT    16384     // B*T
#define NVV   16
#define D     256
#define DIN   4096      // NV*D
#define STRD  264       // padded row stride for 64x256 smem tiles
#define LNEPS 1e-6f

// ---- scratch (device globals: no allocations allowed) ----
__device__ float g_H1[MT * D];      // 16 MB
__device__ float g_H2[MT * D];      // 16 MB
__device__ float g_WGT[MT * NVV];   // 1 MB

// ============================================================================
// Generic tiled GEMM: C[M,256] = act(A[M,K] @ W[K,256] + bias)
// BM=64, 512 threads, per-thread 4x8 microtile. Double-buffered 16-k chunks,
// one barrier per chunk.
// ============================================================================
template<bool ELU>
__global__ __launch_bounds__(512) void gemm_k(const float* __restrict__ A, int K,
                                              const float* __restrict__ W,
                                              const float* __restrict__ bias,
                                              float* __restrict__ C)
{
    __shared__ float sA[2][16 * 65];    // [k][r], stride 65
    __shared__ float sW[2][16 * 256];   // [k][c]
    const int m0  = blockIdx.x * 64;
    const int tid = threadIdx.x;
    const int ty  = tid >> 5, tx = tid & 31;
    const int r0  = ty * 4, c0 = tx * 8;

    float acc[4][8];
#pragma unroll
    for (int i = 0; i < 4; i++)
#pragma unroll
        for (int j = 0; j < 8; j++) acc[i][j] = 0.f;

    const int nc = K >> 4;   // 16-k chunks

    // stage chunk 0 into buffer 0
#pragma unroll
    for (int j = 0; j < 2; j++) {
        int f = tid + j * 512;
        int r = f >> 4, k = f & 15;
        sA[0][k * 65 + r] = A[(size_t)(m0 + r) * K + k];
    }
#pragma unroll
    for (int j = 0; j < 2; j++) {
        int f = tid + j * 512;
        int k = f >> 6, c4 = f & 63;
        *(float4*)&sW[0][k * 256 + c4 * 4] =
            *(const float4*)&W[(size_t)k * 256 + c4 * 4];
    }
    __syncthreads();

    for (int c = 0; c < nc; c++) {
        const int cur = c & 1;
        if (c + 1 < nc) {                       // prefetch next chunk
            const int nxt = cur ^ 1;
            const int k0n = (c + 1) << 4;
#pragma unroll
            for (int j = 0; j < 2; j++) {
                int f = tid + j * 512;
                int r = f >> 4, k = f & 15;
                sA[nxt][k * 65 + r] = A[(size_t)(m0 + r) * K + (k0n + k)];
            }
#pragma unroll
            for (int j = 0; j < 2; j++) {
                int f = tid + j * 512;
                int k = f >> 6, c4 = f & 63;
                *(float4*)&sW[nxt][k * 256 + c4 * 4] =
                    *(const float4*)&W[(size_t)(k0n + k) * 256 + c4 * 4];
            }
        }
#pragma unroll
        for (int k = 0; k < 16; k++) {
            float4 w0 = *(const float4*)&sW[cur][k * 256 + c0];
            float4 w1 = *(const float4*)&sW[cur][k * 256 + c0 + 4];
            float wv[8] = {w0.x, w0.y, w0.z, w0.w, w1.x, w1.y, w1.z, w1.w};
#pragma unroll
            for (int i = 0; i < 4; i++) {
                float a = sA[cur][k * 65 + r0 + i];  // warp-broadcast
#pragma unroll
                for (int j = 0; j < 8; j++) acc[i][j] += a * wv[j];
            }
        }
        __syncthreads();    // readers of 'cur' done; 'nxt' fully staged
    }

    float4 b0 = *(const float4*)&bias[c0];
    float4 b1 = *(const float4*)&bias[c0 + 4];
    float bb[8] = {b0.x, b0.y, b0.z, b0.w, b1.x, b1.y, b1.z, b1.w};
#pragma unroll
    for (int i = 0; i < 4; i++) {
        float v[8];
#pragma unroll
        for (int j = 0; j < 8; j++) v[j] = acc[i][j] + bb[j];
        if (ELU) {
#pragma unroll
            for (int j = 0; j < 8; j++) v[j] = v[j] > 0.f ? v[j] : expm1f(v[j]);
        }
        float4* dst = (float4*)&C[(size_t)(m0 + r0 + i) * 256 + c0];
        dst[0] = make_float4(v[0], v[1], v[2], v[3]);
        dst[1] = make_float4(v[4], v[5], v[6], v[7]);
    }
}

// ============================================================================
// Per-token weight head: logits = LN(GLU(H2@Wg3+bg3) + flat@Wgs+bgs), softmax.
// One CTA (256 thr) per token.
// ============================================================================
__global__ __launch_bounds__(256) void weights_k(
    const float* __restrict__ vars, const float* __restrict__ H2,
    const float* __restrict__ Wg3,  const float* __restrict__ bg3,
    const float* __restrict__ Wgs,  const float* __restrict__ bgs,
    const float* __restrict__ gg,   const float* __restrict__ bgn,
    float* __restrict__ wgt, float* __restrict__ outw)
{
    __shared__ float xrow[DIN];
    __shared__ float h2r[D];
    __shared__ float red[256];
    __shared__ float t3s[32];
    __shared__ float sk[16];
    const int tok = blockIdx.x;
    const int tid = threadIdx.x;

    const float4* src = (const float4*)(vars + (size_t)tok * DIN);
#pragma unroll
    for (int j = 0; j < 4; j++) ((float4*)xrow)[tid + j * 256] = src[tid + j * 256];
    if (tid < 64) ((float4*)h2r)[tid] = ((const float4*)(H2 + (size_t)tok * D))[tid];
    __syncthreads();

    {   // t3[c] = sum_k h2[k] * Wg3[k][c], c in [0,32)
        int part = tid >> 5, c = tid & 31;
        float s = 0.f;
#pragma unroll 8
        for (int j = 0; j < 32; j++) {
            int k = part + 8 * j;
            s += h2r[k] * Wg3[k * 32 + c];
        }
        red[part * 32 + c] = s;
    }
    __syncthreads();
    if (tid < 32) {
        float s = bg3[tid];
#pragma unroll
        for (int j = 0; j < 8; j++) s += red[j * 32 + tid];
        t3s[tid] = s;
    }
    __syncthreads();
    {   // skip[v] = sum_k xrow[k] * Wgs[k][v]
        int part = tid >> 4, v = tid & 15;
        float s = 0.f;
#pragma unroll 8
        for (int j = 0; j < 256; j++) {
            int k = part + 16 * j;
            s += xrow[k] * Wgs[k * 16 + v];
        }
        red[part * 16 + v] = s;
    }
    __syncthreads();
    if (tid < 16) {
        float s = bgs[tid];
#pragma unroll
        for (int j = 0; j < 16; j++) s += red[j * 16 + tid];
        sk[tid] = s;
    }
    __syncthreads();
    if (tid < 16) {
        float a = t3s[tid], b = t3s[16 + tid];
        float g = a * (1.f / (1.f + expf(-b))) + sk[tid];
        float s = g, q = g * g;
#pragma unroll
        for (int o = 8; o; o >>= 1) {
            s += __shfl_xor_sync(0xffffu, s, o, 16);
            q += __shfl_xor_sync(0xffffu, q, o, 16);
        }
        float mean = s * (1.f / 16.f);
        float var  = q * (1.f / 16.f) - mean * mean;
        float wl = (g - mean) * rsqrtf(var + LNEPS) * gg[tid] + bgn[tid];
        float mx = wl;
#pragma unroll
        for (int o = 8; o; o >>= 1) mx = fmaxf(mx, __shfl_xor_sync(0xffffu, mx, o, 16));
        float e = expf(wl - mx);
        float se = e;
#pragma unroll
        for (int o = 8; o; o >>= 1) se += __shfl_xor_sync(0xffffu, se, o, 16);
        float w = e / se;
        wgt[(size_t)tok * NVV + tid]  = w;
        outw[(size_t)tok * NVV + tid] = w;
    }
}

// ============================================================================
// Fused per-variable GRN chain + softmax-weighted combine.
// One CTA per 64-token tile; loops over all 16 variables. Output accumulator
// lives in REGISTERS (per-thread 4x8, same ownership as the GEMM microtile).
// Weight staging double-buffered: one barrier per 16-k chunk.
// ============================================================================
// EPI: 0 = store, 1 = store+elu, 2 = GLU combine (pa in bufOut, +residual)
template<int EPI>
__device__ __forceinline__ void tile_gemm(
    const float* bufIn, float* bufOut, float* sW,   // sW: 2 x 4096 floats
    const float* __restrict__ W, int ldw, int wcol0,
    const float* __restrict__ bias,
    const float* __restrict__ vars, int m0, int v,
    int tid, int r0, int c0)
{
    float acc[4][8];
#pragma unroll
    for (int i = 0; i < 4; i++)
#pragma unroll
        for (int j = 0; j < 8; j++) acc[i][j] = 0.f;

    // stage chunk 0 into buffer 0
#pragma unroll
    for (int j = 0; j < 2; j++) {
        int f = tid + j * 512;
        int k = f >> 6, c4 = f & 63;
        *(float4*)&sW[k * 256 + c4 * 4] =
            *(const float4*)&W[(size_t)k * ldw + wcol0 + c4 * 4];
    }
    __syncthreads();

    for (int c = 0; c < 16; c++) {
        float* sWc = sW + (c & 1) * 4096;
        if (c < 15) {                       // prefetch next chunk
            float* sWn = sW + ((c + 1) & 1) * 4096;
            const int k0n = (c + 1) << 4;
#pragma unroll
            for (int j = 0; j < 2; j++) {
                int f = tid + j * 512;
                int k = f >> 6, c4 = f & 63;
                *(float4*)&sWn[k * 256 + c4 * 4] =
                    *(const float4*)&W[(size_t)(k0n + k) * ldw + wcol0 + c4 * 4];
            }
        }
#pragma unroll
        for (int k = 0; k < 16; k++) {
            float4 w0 = *(const float4*)&sWc[k * 256 + c0];
            float4 w1 = *(const float4*)&sWc[k * 256 + c0 + 4];
            float wv[8] = {w0.x, w0.y, w0.z, w0.w, w1.x, w1.y, w1.z, w1.w};
#pragma unroll
            for (int i = 0; i < 4; i++) {
                float a = bufIn[(r0 + i) * STRD + (c << 4) + k];   // warp-broadcast
#pragma unroll
                for (int j = 0; j < 8; j++) acc[i][j] += a * wv[j];
            }
        }
        __syncthreads();
    }

    float4 b0 = *(const float4*)&bias[c0];
    float4 b1 = *(const float4*)&bias[c0 + 4];
    float bb[8] = {b0.x, b0.y, b0.z, b0.w, b1.x, b1.y, b1.z, b1.w};
#pragma unroll
    for (int i = 0; i < 4; i++) {
        float vv[8];
#pragma unroll
        for (int j = 0; j < 8; j++) vv[j] = acc[i][j] + bb[j];
        if (EPI == 1) {
#pragma unroll
            for (int j = 0; j < 8; j++) vv[j] = vv[j] > 0.f ? vv[j] : expm1f(vv[j]);
        }
        if (EPI <= 1) {
            *(float4*)&bufOut[(r0 + i) * STRD + c0]     = make_float4(vv[0], vv[1], vv[2], vv[3]);
            *(float4*)&bufOut[(r0 + i) * STRD + c0 + 4] = make_float4(vv[4], vv[5], vv[6], vv[7]);
        } else {
            // GLU: g = pa * sigmoid(pb) + x   (pa already in bufOut; vv = pb)
            const float* xp = &vars[(size_t)(m0 + r0 + i) * DIN + v * D + c0];
            float4 x0 = *(const float4*)xp;
            float4 x1 = *(const float4*)(xp + 4);
            float xv[8] = {x0.x, x0.y, x0.z, x0.w, x1.x, x1.y, x1.z, x1.w};
            float* pap = &bufOut[(r0 + i) * STRD + c0];
            float4 p0 = *(float4*)pap;
            float4 p1 = *(float4*)(pap + 4);
            float pv[8] = {p0.x, p0.y, p0.z, p0.w, p1.x, p1.y, p1.z, p1.w};
#pragma unroll
            for (int j = 0; j < 8; j++)
                pv[j] = pv[j] * (1.f / (1.f + expf(-vv[j]))) + xv[j];
            *(float4*)pap       = make_float4(pv[0], pv[1], pv[2], pv[3]);
            *(float4*)(pap + 4) = make_float4(pv[4], pv[5], pv[6], pv[7]);
        }
    }
}

__global__ __launch_bounds__(512) void varchain_k(
    const float* __restrict__ vars,
    const float* __restrict__ Wv1, const float* __restrict__ bv1,
    const float* __restrict__ Wv2, const float* __restrict__ bv2,
    const float* __restrict__ Wv3, const float* __restrict__ bv3,
    const float* __restrict__ gv,  const float* __restrict__ bvn,
    const float* __restrict__ wgt, float* __restrict__ out)
{
    extern __shared__ float sm[];
    float* bufA  = sm;                        // [64][STRD]
    float* bufB  = bufA + 64 * STRD;          // [64][STRD]
    float* sW    = bufB + 64 * STRD;          // [2][16][256] double-buffered
    float* stats = sW + 2 * 16 * 256;         // [64][2] mean,rstd
    float* swr   = stats + 128;               // [64] per-row weight

    const int m0   = blockIdx.x * 64;
    const int tid  = threadIdx.x;
    const int wid  = tid >> 5, lane = tid & 31;
    const int r0   = wid * 4, c0 = lane * 8;

    float outacc[4][8];                       // output accumulator in registers
#pragma unroll
    for (int i = 0; i < 4; i++)
#pragma unroll
        for (int j = 0; j < 8; j++) outacc[i][j] = 0.f;

    for (int v = 0; v < NVV; v++) {
        // load x tile for variable v
#pragma unroll
        for (int j = 0; j < 8; j++) {
            int f = tid + j * 512;
            int r = f >> 6, c4 = f & 63;
            *(float4*)&bufA[r * STRD + c4 * 4] =
                *(const float4*)&vars[(size_t)(m0 + r) * DIN + v * D + c4 * 4];
        }
        if (tid < 64) swr[tid] = wgt[(size_t)(m0 + tid) * NVV + v];
        // (first __syncthreads inside tile_gemm covers these writes)

        tile_gemm<1>(bufA, bufB, sW, Wv1 + (size_t)v * 65536, 256, 0,
                     bv1 + v * 256, vars, m0, v, tid, r0, c0);        // hv1 = elu(x@Wv1+b)
        tile_gemm<0>(bufB, bufA, sW, Wv2 + (size_t)v * 65536, 256, 0,
                     bv2 + v * 256, vars, m0, v, tid, r0, c0);        // hv2 = hv1@Wv2+b
        tile_gemm<0>(bufA, bufB, sW, Wv3 + (size_t)v * 131072, 512, 0,
                     bv3 + v * 512, vars, m0, v, tid, r0, c0);        // pa
        tile_gemm<2>(bufA, bufB, sW, Wv3 + (size_t)v * 131072, 512, 256,
                     bv3 + v * 512 + 256, vars, m0, v, tid, r0, c0);  // pb -> GLU+res
        __syncthreads();

        // LayerNorm over each row of bufB (warp wid owns rows wid*4..wid*4+3)
#pragma unroll
        for (int i = 0; i < 4; i++) {
            int row = wid * 4 + i;
            float s = 0.f, q = 0.f;
#pragma unroll
            for (int j = 0; j < 8; j++) {
                float g = bufB[row * STRD + lane + j * 32];
                s += g; q += g * g;
            }
#pragma unroll
            for (int o = 16; o; o >>= 1) {
                s += __shfl_xor_sync(0xffffffffu, s, o);
                q += __shfl_xor_sync(0xffffffffu, q, o);
            }
            if (lane == 0) {
                float mean = s * (1.f / 256.f);
                float var  = q * (1.f / 256.f) - mean * mean;
                stats[row * 2]     = mean;
                stats[row * 2 + 1] = rsqrtf(var + LNEPS);
            }
        }
        __syncthreads();

        // normalize, scale, weighted-accumulate into register outacc
        float4 gva = *(const float4*)&gv[v * D + c0];
        float4 gvb = *(const float4*)&gv[v * D + c0 + 4];
        float4 bna = *(const float4*)&bvn[v * D + c0];
        float4 bnb = *(const float4*)&bvn[v * D + c0 + 4];
        float gvv[8] = {gva.x, gva.y, gva.z, gva.w, gvb.x, gvb.y, gvb.z, gvb.w};
        float bnv[8] = {bna.x, bna.y, bna.z, bna.w, bnb.x, bnb.y, bnb.z, bnb.w};
#pragma unroll
        for (int i = 0; i < 4; i++) {
            int row = r0 + i;
            float mean = stats[row * 2], rstd = stats[row * 2 + 1], w = swr[row];
            float4 ga = *(float4*)&bufB[row * STRD + c0];
            float4 gb = *(float4*)&bufB[row * STRD + c0 + 4];
            float gvals[8] = {ga.x, ga.y, ga.z, ga.w, gb.x, gb.y, gb.z, gb.w};
#pragma unroll
            for (int j = 0; j < 8; j++)
                outacc[i][j] += ((gvals[j] - mean) * rstd * gvv[j] + bnv[j]) * w;
        }
        __syncthreads();   // protect swr/bufA/bufB for next v
    }

    // write out tile from registers (coalesced: lane covers 8 consecutive floats)
#pragma unroll
    for (int i = 0; i < 4; i++) {
        float4* dst = (float4*)&out[(size_t)(m0 + r0 + i) * D + c0];
        dst[0] = make_float4(outacc[i][0], outacc[i][1], outacc[i][2], outacc[i][3]);
        dst[1] = make_float4(outacc[i][4], outacc[i][5], outacc[i][6], outacc[i][7]);
    }
}

// ============================================================================
// Launch
// ============================================================================
extern "C" void kernel_launch(void* const* d_in, const int* in_sizes, int n_in,
                              void* d_out, int out_size)
{
    const float* vars = (const float*)d_in[0];
    const float* Wg1  = (const float*)d_in[1];
    const float* bg1  = (const float*)d_in[2];
    const float* Wg2  = (const float*)d_in[3];
    const float* bg2  = (const float*)d_in[4];
    const float* Wg3  = (const float*)d_in[5];
    const float* bg3  = (const float*)d_in[6];
    const float* Wgs  = (const float*)d_in[7];
    const float* bgs  = (const float*)d_in[8];
    const float* gg   = (const float*)d_in[9];
    const float* bgn  = (const float*)d_in[10];
    const float* Wv1  = (const float*)d_in[11];
    const float* bv1  = (const float*)d_in[12];
    const float* Wv2  = (const float*)d_in[13];
    const float* bv2  = (const float*)d_in[14];
    const float* Wv3  = (const float*)d_in[15];
    const float* bv3  = (const float*)d_in[16];
    const float* gv   = (const float*)d_in[17];
    const float* bvn  = (const float*)d_in[18];

    float* out  = (float*)d_out;                      // [MT, D]
    float* outw = out + (size_t)MT * D;               // [MT, NV] (weight output)

    float *H1, *H2, *WGT;
    cudaGetSymbolAddress((void**)&H1, g_H1);
    cudaGetSymbolAddress((void**)&H2, g_H2);
    cudaGetSymbolAddress((void**)&WGT, g_WGT);

    const int smem4 = (2 * 64 * STRD + 2 * 16 * 256 + 128 + 64) * (int)sizeof(float);
    cudaFuncSetAttribute(varchain_k, cudaFuncAttributeMaxDynamicSharedMemorySize, smem4);

    gemm_k<true ><<<MT / 64, 512>>>(vars, DIN, Wg1, bg1, H1);   // H1 = elu(flat@Wg1+b)
    gemm_k<false><<<MT / 64, 512>>>(H1,   D,   Wg2, bg2, H2);   // H2 = H1@Wg2+b
    weights_k<<<MT, 256>>>(vars, H2, Wg3, bg3, Wgs, bgs, gg, bgn, WGT, outw);
    varchain_k<<<MT / 64, 512, smem4>>>(vars, Wv1, bv1, Wv2, bv2, Wv3, bv3,
                                        gv, bvn, WGT, out);
}

// round 14
// speedup vs baseline: 1.3760x; 1.3760x over previous
#include <cuda_runtime.h>
#include <math.h>

#define MT    16384     // B*T
#define NVV   16
#define D     256
#define DIN   4096      // NV*D
#define STRD  256       // row stride for 64x256 smem tiles (reads broadcast / lane-consecutive -> no pad needed)
#define LNEPS 1e-6f

// ---- scratch (device globals: no allocations allowed) ----
__device__ float g_H1[MT * D];      // 16 MB
__device__ float g_H2[MT * D];      // 16 MB
__device__ float g_WGT[MT * NVV];   // 1 MB

// ---- packed f32x2 helpers (FFMA2: only reachable via PTX fma.rn.f32x2) ----
__device__ __forceinline__ unsigned long long pk2(float x) {
    unsigned long long r;
    asm("mov.b64 %0, {%1, %1};" : "=l"(r) : "f"(x));
    return r;
}
__device__ __forceinline__ void fma2(unsigned long long& d,
                                     unsigned long long a, unsigned long long b) {
    asm("fma.rn.f32x2 %0, %1, %2, %0;" : "+l"(d) : "l"(a), "l"(b));
}
__device__ __forceinline__ void upk2(float& lo, float& hi, unsigned long long v) {
    asm("mov.b64 {%0, %1}, %2;" : "=f"(lo), "=f"(hi) : "l"(v));
}

// Thread column mapping: two 4-col blocks, cA = lane*4, cB = 128 + lane*4.
// -> all W LDS.128 conflict-free, all global stores coalesced.

// ============================================================================
// Generic tiled GEMM: C[M,256] = act(A[M,K] @ W[K,256] + bias)
// BM=64, 512 threads, per-thread 4 rows x (4+4) cols, f32x2 packed FMA.
// Double-buffered 16-k chunks, one barrier per chunk.
// ============================================================================
template<bool ELU>
__global__ __launch_bounds__(512) void gemm_k(const float* __restrict__ A, int K,
                                              const float* __restrict__ W,
                                              const float* __restrict__ bias,
                                              float* __restrict__ C)
{
    __shared__ float sA[2][64 * 16];    // [r][k] row-major, 16 k per chunk
    __shared__ float sW[2][16 * 256];   // [k][c]
    const int m0   = blockIdx.x * 64;
    const int tid  = threadIdx.x;
    const int wid  = tid >> 5, lane = tid & 31;
    const int r0   = wid * 4;
    const int cA   = lane * 4, cB = 128 + lane * 4;

    unsigned long long acc2[4][4];      // [row][pair]: pairs 0,1 -> cA; 2,3 -> cB
#pragma unroll
    for (int i = 0; i < 4; i++)
#pragma unroll
        for (int p = 0; p < 4; p++) acc2[i][p] = 0ULL;

    const int nc = K >> 4;

    // stage chunk 0
    if (tid < 256) {
        int r = tid >> 2, kq = tid & 3;
        *(float4*)&sA[0][r * 16 + kq * 4] =
            *(const float4*)&A[(size_t)(m0 + r) * K + kq * 4];
    }
#pragma unroll
    for (int j = 0; j < 2; j++) {
        int f = tid + j * 512;
        int k = f >> 6, c4 = f & 63;
        *(float4*)&sW[0][k * 256 + c4 * 4] =
            *(const float4*)&W[(size_t)k * 256 + c4 * 4];
    }
    __syncthreads();

    for (int c = 0; c < nc; c++) {
        const int cur = c & 1;
        if (c + 1 < nc) {                       // prefetch next chunk
            const int nxt = cur ^ 1;
            const int k0n = (c + 1) << 4;
            if (tid < 256) {
                int r = tid >> 2, kq = tid & 3;
                *(float4*)&sA[nxt][r * 16 + kq * 4] =
                    *(const float4*)&A[(size_t)(m0 + r) * K + k0n + kq * 4];
            }
#pragma unroll
            for (int j = 0; j < 2; j++) {
                int f = tid + j * 512;
                int k = f >> 6, c4 = f & 63;
                *(float4*)&sW[nxt][k * 256 + c4 * 4] =
                    *(const float4*)&W[(size_t)(k0n + k) * 256 + c4 * 4];
            }
        }
#pragma unroll
        for (int kq = 0; kq < 4; kq++) {
            float4 av[4];
#pragma unroll
            for (int i = 0; i < 4; i++)         // broadcast LDS.128 (1 per row per 4k)
                av[i] = *(const float4*)&sA[cur][(r0 + i) * 16 + kq * 4];
#pragma unroll
            for (int kk = 0; kk < 4; kk++) {
                int kidx = kq * 4 + kk;
                ulonglong2 wA = *(const ulonglong2*)&sW[cur][kidx * 256 + cA];
                ulonglong2 wB = *(const ulonglong2*)&sW[cur][kidx * 256 + cB];
#pragma unroll
                for (int i = 0; i < 4; i++) {
                    const float* avp = (const float*)&av[i];
                    unsigned long long ap = pk2(avp[kk]);
                    fma2(acc2[i][0], ap, wA.x);
                    fma2(acc2[i][1], ap, wA.y);
                    fma2(acc2[i][2], ap, wB.x);
                    fma2(acc2[i][3], ap, wB.y);
                }
            }
        }
        __syncthreads();
    }

    float4 ba = *(const float4*)&bias[cA];
    float4 bb = *(const float4*)&bias[cB];
    const float* bap = (const float*)&ba;
    const float* bbp = (const float*)&bb;
#pragma unroll
    for (int i = 0; i < 4; i++) {
        float v[8];
        upk2(v[0], v[1], acc2[i][0]);
        upk2(v[2], v[3], acc2[i][1]);
        upk2(v[4], v[5], acc2[i][2]);
        upk2(v[6], v[7], acc2[i][3]);
#pragma unroll
        for (int j = 0; j < 4; j++) { v[j] += bap[j]; v[4 + j] += bbp[j]; }
        if (ELU) {
#pragma unroll
            for (int j = 0; j < 8; j++) v[j] = v[j] > 0.f ? v[j] : expm1f(v[j]);
        }
        float* dst = &C[(size_t)(m0 + r0 + i) * 256];
        *(float4*)&dst[cA] = make_float4(v[0], v[1], v[2], v[3]);
        *(float4*)&dst[cB] = make_float4(v[4], v[5], v[6], v[7]);
    }
}

// ============================================================================
// Per-token weight head: logits = LN(GLU(H2@Wg3+bg3) + flat@Wgs+bgs), softmax.
// One CTA (256 thr) per token.
// ============================================================================
__global__ __launch_bounds__(256) void weights_k(
    const float* __restrict__ vars, const float* __restrict__ H2,
    const float* __restrict__ Wg3,  const float* __restrict__ bg3,
    const float* __restrict__ Wgs,  const float* __restrict__ bgs,
    const float* __restrict__ gg,   const float* __restrict__ bgn,
    float* __restrict__ wgt, float* __restrict__ outw)
{
    __shared__ float xrow[DIN];
    __shared__ float h2r[D];
    __shared__ float red[256];
    __shared__ float t3s[32];
    __shared__ float sk[16];
    const int tok = blockIdx.x;
    const int tid = threadIdx.x;

    const float4* src = (const float4*)(vars + (size_t)tok * DIN);
#pragma unroll
    for (int j = 0; j < 4; j++) ((float4*)xrow)[tid + j * 256] = src[tid + j * 256];
    if (tid < 64) ((float4*)h2r)[tid] = ((const float4*)(H2 + (size_t)tok * D))[tid];
    __syncthreads();

    {   // t3[c] = sum_k h2[k] * Wg3[k][c], c in [0,32)
        int part = tid >> 5, c = tid & 31;
        float s = 0.f;
#pragma unroll 8
        for (int j = 0; j < 32; j++) {
            int k = part + 8 * j;
            s += h2r[k] * Wg3[k * 32 + c];
        }
        red[part * 32 + c] = s;
    }
    __syncthreads();
    if (tid < 32) {
        float s = bg3[tid];
#pragma unroll
        for (int j = 0; j < 8; j++) s += red[j * 32 + tid];
        t3s[tid] = s;
    }
    __syncthreads();
    {   // skip[v] = sum_k xrow[k] * Wgs[k][v]
        int part = tid >> 4, v = tid & 15;
        float s = 0.f;
#pragma unroll 8
        for (int j = 0; j < 256; j++) {
            int k = part + 16 * j;
            s += xrow[k] * Wgs[k * 16 + v];
        }
        red[part * 16 + v] = s;
    }
    __syncthreads();
    if (tid < 16) {
        float s = bgs[tid];
#pragma unroll
        for (int j = 0; j < 16; j++) s += red[j * 16 + tid];
        sk[tid] = s;
    }
    __syncthreads();
    if (tid < 16) {
        float a = t3s[tid], b = t3s[16 + tid];
        float g = a * (1.f / (1.f + expf(-b))) + sk[tid];
        float s = g, q = g * g;
#pragma unroll
        for (int o = 8; o; o >>= 1) {
            s += __shfl_xor_sync(0xffffu, s, o, 16);
            q += __shfl_xor_sync(0xffffu, q, o, 16);
        }
        float mean = s * (1.f / 16.f);
        float var  = q * (1.f / 16.f) - mean * mean;
        float wl = (g - mean) * rsqrtf(var + LNEPS) * gg[tid] + bgn[tid];
        float mx = wl;
#pragma unroll
        for (int o = 8; o; o >>= 1) mx = fmaxf(mx, __shfl_xor_sync(0xffffu, mx, o, 16));
        float e = expf(wl - mx);
        float se = e;
#pragma unroll
        for (int o = 8; o; o >>= 1) se += __shfl_xor_sync(0xffffu, se, o, 16);
        float w = e / se;
        wgt[(size_t)tok * NVV + tid]  = w;
        outw[(size_t)tok * NVV + tid] = w;
    }
}

// ============================================================================
// Fused per-variable GRN chain + softmax-weighted combine.
// One CTA per 64-token tile, f32x2 packed FMA, conflict-free column mapping,
// output accumulator in smem (keeps regs < 128 -> no spill).
// ============================================================================
// EPI: 0 = store, 1 = store+elu, 2 = GLU combine (pa in bufOut, +residual)
template<int EPI>
__device__ __forceinline__ void tile_gemm(
    const float* bufIn, float* bufOut, float* sW,   // sW: 2 x 4096 floats
    const float* __restrict__ W, int ldw, int wcol0,
    const float* __restrict__ bias,
    const float* __restrict__ vars, int m0, int v,
    int tid, int r0, int cA, int cB)
{
    unsigned long long acc2[4][4];
#pragma unroll
    for (int i = 0; i < 4; i++)
#pragma unroll
        for (int p = 0; p < 4; p++) acc2[i][p] = 0ULL;

    // stage chunk 0 into buffer 0
#pragma unroll
    for (int j = 0; j < 2; j++) {
        int f = tid + j * 512;
        int k = f >> 6, c4 = f & 63;
        *(float4*)&sW[k * 256 + c4 * 4] =
            *(const float4*)&W[(size_t)k * ldw + wcol0 + c4 * 4];
    }
    __syncthreads();

    for (int c = 0; c < 16; c++) {
        const float* sWc = sW + (c & 1) * 4096;
        if (c < 15) {                       // prefetch next chunk
            float* sWn = sW + ((c + 1) & 1) * 4096;
            const int k0n = (c + 1) << 4;
#pragma unroll
            for (int j = 0; j < 2; j++) {
                int f = tid + j * 512;
                int k = f >> 6, c4 = f & 63;
                *(float4*)&sWn[k * 256 + c4 * 4] =
                    *(const float4*)&W[(size_t)(k0n + k) * ldw + wcol0 + c4 * 4];
            }
        }
#pragma unroll
        for (int kq = 0; kq < 4; kq++) {
            float4 av[4];
#pragma unroll
            for (int i = 0; i < 4; i++)         // broadcast LDS.128
                av[i] = *(const float4*)&bufIn[(r0 + i) * STRD + (c << 4) + kq * 4];
#pragma unroll
            for (int kk = 0; kk < 4; kk++) {
                int kidx = kq * 4 + kk;
                ulonglong2 wA = *(const ulonglong2*)&sWc[kidx * 256 + cA];
                ulonglong2 wB = *(const ulonglong2*)&sWc[kidx * 256 + cB];
#pragma unroll
                for (int i = 0; i < 4; i++) {
                    const float* avp = (const float*)&av[i];
                    unsigned long long ap = pk2(avp[kk]);
                    fma2(acc2[i][0], ap, wA.x);
                    fma2(acc2[i][1], ap, wA.y);
                    fma2(acc2[i][2], ap, wB.x);
                    fma2(acc2[i][3], ap, wB.y);
                }
            }
        }
        __syncthreads();
    }

    float4 ba = *(const float4*)&bias[cA];
    float4 bb = *(const float4*)&bias[cB];
    const float* bap = (const float*)&ba;
    const float* bbp = (const float*)&bb;
#pragma unroll
    for (int i = 0; i < 4; i++) {
        float vv[8];
        upk2(vv[0], vv[1], acc2[i][0]);
        upk2(vv[2], vv[3], acc2[i][1]);
        upk2(vv[4], vv[5], acc2[i][2]);
        upk2(vv[6], vv[7], acc2[i][3]);
#pragma unroll
        for (int j = 0; j < 4; j++) { vv[j] += bap[j]; vv[4 + j] += bbp[j]; }
        if (EPI == 1) {
#pragma unroll
            for (int j = 0; j < 8; j++) vv[j] = vv[j] > 0.f ? vv[j] : expm1f(vv[j]);
        }
        float* row = &bufOut[(r0 + i) * STRD];
        if (EPI <= 1) {
            *(float4*)&row[cA] = make_float4(vv[0], vv[1], vv[2], vv[3]);
            *(float4*)&row[cB] = make_float4(vv[4], vv[5], vv[6], vv[7]);
        } else {
            // GLU: g = pa * sigmoid(pb) + x   (pa already in bufOut; vv = pb)
            const float* xp = &vars[(size_t)(m0 + r0 + i) * DIN + v * D];
            float4 xa = *(const float4*)&xp[cA];
            float4 xb = *(const float4*)&xp[cB];
            float4 pa = *(float4*)&row[cA];
            float4 pb = *(float4*)&row[cB];
            const float* xap = (const float*)&xa;
            const float* xbp = (const float*)&xb;
            float* pap = (float*)&pa;
            float* pbp = (float*)&pb;
#pragma unroll
            for (int j = 0; j < 4; j++) {
                pap[j] = pap[j] * (1.f / (1.f + expf(-vv[j])))     + xap[j];
                pbp[j] = pbp[j] * (1.f / (1.f + expf(-vv[4 + j]))) + xbp[j];
            }
            *(float4*)&row[cA] = pa;
            *(float4*)&row[cB] = pb;
        }
    }
}

__global__ __launch_bounds__(512) void varchain_k(
    const float* __restrict__ vars,
    const float* __restrict__ Wv1, const float* __restrict__ bv1,
    const float* __restrict__ Wv2, const float* __restrict__ bv2,
    const float* __restrict__ Wv3, const float* __restrict__ bv3,
    const float* __restrict__ gv,  const float* __restrict__ bvn,
    const float* __restrict__ wgt, float* __restrict__ out)
{
    extern __shared__ float sm[];
    float* bufA  = sm;                        // [64][256]
    float* bufB  = bufA + 64 * STRD;          // [64][256]
    float* bufC  = bufB + 64 * STRD;          // [64][256] output accumulator
    float* sW    = bufC + 64 * 256;           // [2][16][256] double-buffered
    float* stats = sW + 2 * 16 * 256;         // [64][2] mean,rstd
    float* swr   = stats + 128;               // [64] per-row weight

    const int m0   = blockIdx.x * 64;
    const int tid  = threadIdx.x;
    const int wid  = tid >> 5, lane = tid & 31;
    const int r0   = wid * 4;
    const int cA   = lane * 4, cB = 128 + lane * 4;

    for (int f = tid; f < 64 * 256; f += 512) bufC[f] = 0.f;

    for (int v = 0; v < NVV; v++) {
        // load x tile for variable v
#pragma unroll
        for (int j = 0; j < 8; j++) {
            int f = tid + j * 512;
            int r = f >> 6, c4 = f & 63;
            *(float4*)&bufA[r * STRD + c4 * 4] =
                *(const float4*)&vars[(size_t)(m0 + r) * DIN + v * D + c4 * 4];
        }
        if (tid < 64) swr[tid] = wgt[(size_t)(m0 + tid) * NVV + v];
        // (first __syncthreads inside tile_gemm covers these writes)

        tile_gemm<1>(bufA, bufB, sW, Wv1 + (size_t)v * 65536, 256, 0,
                     bv1 + v * 256, vars, m0, v, tid, r0, cA, cB);        // hv1 = elu(x@Wv1+b)
        tile_gemm<0>(bufB, bufA, sW, Wv2 + (size_t)v * 65536, 256, 0,
                     bv2 + v * 256, vars, m0, v, tid, r0, cA, cB);        // hv2 = hv1@Wv2+b
        tile_gemm<0>(bufA, bufB, sW, Wv3 + (size_t)v * 131072, 512, 0,
                     bv3 + v * 512, vars, m0, v, tid, r0, cA, cB);        // pa
        tile_gemm<2>(bufA, bufB, sW, Wv3 + (size_t)v * 131072, 512, 256,
                     bv3 + v * 512 + 256, vars, m0, v, tid, r0, cA, cB);  // pb -> GLU+res
        __syncthreads();

        // LayerNorm over each row of bufB (warp wid owns rows wid*4..wid*4+3)
#pragma unroll
        for (int i = 0; i < 4; i++) {
            int row = wid * 4 + i;
            float s = 0.f, q = 0.f;
#pragma unroll
            for (int j = 0; j < 8; j++) {
                float g = bufB[row * STRD + lane + j * 32];
                s += g; q += g * g;
            }
#pragma unroll
            for (int o = 16; o; o >>= 1) {
                s += __shfl_xor_sync(0xffffffffu, s, o);
                q += __shfl_xor_sync(0xffffffffu, q, o);
            }
            if (lane == 0) {
                float mean = s * (1.f / 256.f);
                float var  = q * (1.f / 256.f) - mean * mean;
                stats[row * 2]     = mean;
                stats[row * 2 + 1] = rsqrtf(var + LNEPS);
            }
        }
        __syncthreads();

        // normalize, scale, weighted-accumulate into bufC
        float4 gva = *(const float4*)&gv[v * D + cA];
        float4 gvb = *(const float4*)&gv[v * D + cB];
        float4 bna = *(const float4*)&bvn[v * D + cA];
        float4 bnb = *(const float4*)&bvn[v * D + cB];
        const float* gvap = (const float*)&gva;
        const float* gvbp = (const float*)&gvb;
        const float* bnap = (const float*)&bna;
        const float* bnbp = (const float*)&bnb;
#pragma unroll
        for (int i = 0; i < 4; i++) {
            int row = r0 + i;
            float mean = stats[row * 2], rstd = stats[row * 2 + 1], w = swr[row];
            float4 ga = *(float4*)&bufB[row * STRD + cA];
            float4 gb = *(float4*)&bufB[row * STRD + cB];
            float4 ca = *(float4*)&bufC[row * 256 + cA];
            float4 cb = *(float4*)&bufC[row * 256 + cB];
            const float* gap = (const float*)&ga;
            const float* gbp = (const float*)&gb;
            float* cap = (float*)&ca;
            float* cbp = (float*)&cb;
#pragma unroll
            for (int j = 0; j < 4; j++) {
                cap[j] += ((gap[j] - mean) * rstd * gvap[j] + bnap[j]) * w;
                cbp[j] += ((gbp[j] - mean) * rstd * gvbp[j] + bnbp[j]) * w;
            }
            *(float4*)&bufC[row * 256 + cA] = ca;
            *(float4*)&bufC[row * 256 + cB] = cb;
        }
        __syncthreads();   // protect swr/bufA/bufB/bufC for next v
    }

    // write out tile
#pragma unroll
    for (int j = 0; j < 8; j++) {
        int f = tid + j * 512;
        int r = f >> 6, c4 = f & 63;
        *(float4*)&out[(size_t)(m0 + r) * D + c4 * 4] =
            *(float4*)&bufC[r * 256 + c4 * 4];
    }
}

// ============================================================================
// Launch
// ============================================================================
extern "C" void kernel_launch(void* const* d_in, const int* in_sizes, int n_in,
                              void* d_out, int out_size)
{
    const float* vars = (const float*)d_in[0];
    const float* Wg1  = (const float*)d_in[1];
    const float* bg1  = (const float*)d_in[2];
    const float* Wg2  = (const float*)d_in[3];
    const float* bg2  = (const float*)d_in[4];
    const float* Wg3  = (const float*)d_in[5];
    const float* bg3  = (const float*)d_in[6];
    const float* Wgs  = (const float*)d_in[7];
    const float* bgs  = (const float*)d_in[8];
    const float* gg   = (const float*)d_in[9];
    const float* bgn  = (const float*)d_in[10];
    const float* Wv1  = (const float*)d_in[11];
    const float* bv1  = (const float*)d_in[12];
    const float* Wv2  = (const float*)d_in[13];
    const float* bv2  = (const float*)d_in[14];
    const float* Wv3  = (const float*)d_in[15];
    const float* bv3  = (const float*)d_in[16];
    const float* gv   = (const float*)d_in[17];
    const float* bvn  = (const float*)d_in[18];

    float* out  = (float*)d_out;                      // [MT, D]
    float* outw = out + (size_t)MT * D;               // [MT, NV] (weight output)

    float *H1, *H2, *WGT;
    cudaGetSymbolAddress((void**)&H1, g_H1);
    cudaGetSymbolAddress((void**)&H2, g_H2);
    cudaGetSymbolAddress((void**)&WGT, g_WGT);

    const int smem4 = (3 * 64 * STRD + 2 * 16 * 256 + 128 + 64) * (int)sizeof(float);
    cudaFuncSetAttribute(varchain_k, cudaFuncAttributeMaxDynamicSharedMemorySize, smem4);

    gemm_k<true ><<<MT / 64, 512>>>(vars, DIN, Wg1, bg1, H1);   // H1 = elu(flat@Wg1+b)
    gemm_k<false><<<MT / 64, 512>>>(H1,   D,   Wg2, bg2, H2);   // H2 = H1@Wg2+b
    weights_k<<<MT, 256>>>(vars, H2, Wg3, bg3, Wgs, bgs, gg, bgn, WGT, outw);
    varchain_k<<<MT / 64, 512, smem4>>>(vars, Wv1, bv1, Wv2, bv2, Wv3, bv3,
                                        gv, bvn, WGT, out);
}